// round 4
// baseline (speedup 1.0000x reference)
#include <cuda_runtime.h>
#include <math.h>

#define BATCH 32
#define P 250000
#define TOPK 200
#define BINS 4096
#define CAP 4096
#define NMS_THR 0.45f
#define CONF_THR 0.01f

// ---------------- scratch (device globals: no allocation allowed) ----------------
__device__ unsigned short     g_key16[(size_t)BATCH * P];   // 16 MB (d-key top bits)
__device__ unsigned int       g_hist[BATCH * BINS];
__device__ int                g_thresh[BATCH];
__device__ int                g_count[BATCH];
__device__ unsigned long long g_cand[BATCH * CAP];

// sortable key for d (possibly negative): larger float -> larger uint
__device__ __forceinline__ unsigned f2key(float f) {
    unsigned b = __float_as_uint(f);
    return (b & 0x80000000u) ? ~b : (b | 0x80000000u);
}

// Replicate XLA softmax(conf)[:,1] rounding exactly:
//   m = max(c0,c1); e_i = exp(c_i - m)  [libdevice __nv_expf];
//   s = e1 / (e0 + e1)  with IEEE add/div.
__device__ __forceinline__ float xla_score(float c0, float c1) {
    if (c1 >= c0) {
        float e0 = expf(__fsub_rn(c0, c1));           // e1 = exp(0) = 1
        return __fdiv_rn(1.0f, __fadd_rn(e0, 1.0f));
    } else {
        float e1 = expf(__fsub_rn(c1, c0));           // e0 = 1
        return __fdiv_rn(e1, __fadd_rn(1.0f, e1));
    }
}

// ---------------- K0: zero hist + counters ----------------
__global__ void k_zero() {
    int i = blockIdx.x * blockDim.x + threadIdx.x;
    if (i < BATCH * BINS) g_hist[i] = 0u;
    if (i < BATCH)        g_count[i] = 0;
}

// ---------------- K1: stream conf, write 16-bit d-keys + 12-bit histogram ----------------
__global__ void k_keys_hist(const float* __restrict__ conf) {
    const int b = blockIdx.y;
    __shared__ unsigned int sh[BINS];
    for (int i = threadIdx.x; i < BINS; i += blockDim.x) sh[i] = 0u;
    __syncthreads();

    const float2* cp = (const float2*)(conf + (size_t)b * P * 2);
    const int stride = gridDim.x * blockDim.x;
    for (int i = blockIdx.x * blockDim.x + threadIdx.x; i < P; i += stride) {
        float2 c = cp[i];
        unsigned key = f2key(__fsub_rn(c.y, c.x));
        g_key16[(size_t)b * P + i] = (unsigned short)(key >> 16);
        atomicAdd(&sh[key >> 20], 1u);
    }
    __syncthreads();
    for (int i = threadIdx.x; i < BINS; i += blockDim.x) {
        unsigned v = sh[i];
        if (v) atomicAdd(&g_hist[b * BINS + i], v);
    }
}

// ---------------- K2: per-batch threshold bin (count(bin' >= bin) >= TOPK) ----------------
__global__ void k_thresh() {
    const int b = blockIdx.x;
    __shared__ unsigned sh[BINS];
    __shared__ unsigned part[256];
    const int t = threadIdx.x;

    for (int i = t; i < BINS; i += 256) sh[i] = g_hist[b * BINS + i];
    __syncthreads();

    const int hi = BINS - 1 - t * 16;
    unsigned s = 0;
    #pragma unroll
    for (int j = 0; j < 16; j++) s += sh[hi - j];
    part[t] = s;
    __syncthreads();

    for (int off = 1; off < 256; off <<= 1) {
        unsigned v = (t >= off) ? part[t - off] : 0u;
        __syncthreads();
        part[t] += v;
        __syncthreads();
    }

    unsigned cum  = part[t];
    unsigned prev = (t == 0) ? 0u : part[t - 1];
    if (cum >= TOPK && prev < TOPK) {
        unsigned acc = prev;
        int bin = hi;
        #pragma unroll
        for (int j = 0; j < 16; j++) {
            acc += sh[hi - j];
            if (acc >= TOPK) { bin = hi - j; break; }
        }
        g_thresh[b] = bin;
    }
}

// ---------------- K3: collect candidates with SCORE-based composite key ----------------
__global__ void k_collect(const float* __restrict__ conf) {
    const int b = blockIdx.y;
    const int th = g_thresh[b];
    const float2* cp = (const float2*)(conf + (size_t)b * P * 2);
    const int stride = gridDim.x * blockDim.x;
    for (int i = blockIdx.x * blockDim.x + threadIdx.x; i < P; i += stride) {
        unsigned k16 = (unsigned)g_key16[(size_t)b * P + i];
        if ((int)(k16 >> 4) >= th) {
            float2 c = cp[i];
            float sc = xla_score(c.x, c.y);            // in (0,1): bits monotone
            unsigned long long comp =
                ((unsigned long long)__float_as_uint(sc) << 32) |
                (unsigned long long)(0xFFFFFFFFu - (unsigned)i); // score desc, idx asc on tie
            int pos = atomicAdd(&g_count[b], 1);
            if (pos < CAP) g_cand[b * CAP + pos] = comp;
        }
    }
}

// ---------------- K4: sort, decode, NMS, write ----------------
__global__ __launch_bounds__(512) void k_final(const float* __restrict__ loc,
                                               const float* __restrict__ priors,
                                               float* __restrict__ out) {
    const int b = blockIdx.x;
    const int t = threadIdx.x;

    __shared__ unsigned long long sc[CAP];
    __shared__ float    sbox[TOPK * 4];
    __shared__ float    sscore[TOPK];
    __shared__ unsigned smask[TOPK * 7];
    __shared__ int      skeep[TOPK];

    int n = g_count[b];
    if (n > CAP) n = CAP;
    int m = 256;
    while (m < n) m <<= 1;

    for (int i = t; i < m; i += 512) sc[i] = (i < n) ? g_cand[b * CAP + i] : 0ull;
    __syncthreads();

    // bitonic sort descending on (score_bits, ~idx)
    for (int k2 = 2; k2 <= m; k2 <<= 1) {
        for (int j = k2 >> 1; j > 0; j >>= 1) {
            for (int i = t; i < m; i += 512) {
                int ixj = i ^ j;
                if (ixj > i) {
                    unsigned long long a = sc[i], c = sc[ixj];
                    bool sw = ((i & k2) == 0) ? (a < c) : (a > c);
                    if (sw) { sc[i] = c; sc[ixj] = a; }
                }
            }
            __syncthreads();
        }
    }

    // top-200: decode box + score
    if (t < TOPK) {
        unsigned long long c = sc[t];
        float score  = __uint_as_float((unsigned)(c >> 32));
        unsigned idx = 0xFFFFFFFFu - (unsigned)(c & 0xFFFFFFFFull);

        const float* l  = loc + ((size_t)b * P + idx) * 4;
        const float* pr = priors + (size_t)idx * 4;
        float px0 = pr[0], py0 = pr[1], px1 = pr[2], py1 = pr[3];
        float pw = px1 - px0, ph = py1 - py0;
        float pcx = (px0 + px1) * 0.5f, pcy = (py0 + py1) * 0.5f;
        float l0 = l[0], l1 = l[1], l2 = l[2], l3 = l[3];
        float cx = pcx + l0 * pw;
        float cy = pcy + l1 * ph;
        float w  = pw * expf(l2);
        float h  = ph * expf(l3);
        sbox[t * 4 + 0] = cx - w * 0.5f;
        sbox[t * 4 + 1] = cy - h * 0.5f;
        sbox[t * 4 + 2] = cx + w * 0.5f;
        sbox[t * 4 + 3] = cy + h * 0.5f;
        sscore[t] = score;
    }
    for (int i = t; i < TOPK * 7; i += 512) smask[i] = 0u;
    __syncthreads();

    // IoU suppression bitmask (j < i, iou > thr)
    for (int p = t; p < TOPK * TOPK; p += 512) {
        int i = p / TOPK, j = p % TOPK;
        if (j < i) {
            float ax0 = sbox[i * 4 + 0], ay0 = sbox[i * 4 + 1];
            float ax1 = sbox[i * 4 + 2], ay1 = sbox[i * 4 + 3];
            float bx0 = sbox[j * 4 + 0], by0 = sbox[j * 4 + 1];
            float bx1 = sbox[j * 4 + 2], by1 = sbox[j * 4 + 3];
            float iw = fminf(ax1, bx1) - fmaxf(ax0, bx0); iw = fmaxf(iw, 0.0f);
            float ih = fminf(ay1, by1) - fmaxf(ay0, by0); ih = fmaxf(ih, 0.0f);
            float inter = iw * ih;
            float aa = fmaxf(ax1 - ax0, 0.0f) * fmaxf(ay1 - ay0, 0.0f);
            float ab = fmaxf(bx1 - bx0, 0.0f) * fmaxf(by1 - by0, 0.0f);
            float uni = fmaxf(aa + ab - inter, 1e-9f);
            if (inter / uni > NMS_THR)
                atomicOr(&smask[i * 7 + (j >> 5)], 1u << (j & 31));
        }
    }
    __syncthreads();

    // greedy NMS on warp 0: lane w owns keep-bit word w (w < 7)
    if (t < 32) {
        unsigned kw = 0u;
        for (int i = 0; i < TOPK; i++) {
            bool sup = (t < 7) && ((smask[i * 7 + t] & kw) != 0u);
            sup = __any_sync(0xffffffffu, sup);
            bool kp = (sscore[i] > CONF_THR) && !sup;
            if (t == (i >> 5) && kp) kw |= 1u << (i & 31);
            if (t == 0) skeep[i] = kp ? 1 : 0;
        }
    }
    __syncthreads();

    // write output [B,2,TOPK,5]: class 0 all zero, class 1 = det * keep
    float* ob = out + (size_t)b * 2 * TOPK * 5;
    for (int i = t; i < TOPK * 5; i += 512) ob[i] = 0.0f;
    if (t < TOPK) {
        float f = skeep[t] ? 1.0f : 0.0f;
        float* r = ob + TOPK * 5 + t * 5;
        r[0] = sscore[t] * f;
        r[1] = sbox[t * 4 + 0] * f;
        r[2] = sbox[t * 4 + 1] * f;
        r[3] = sbox[t * 4 + 2] * f;
        r[4] = sbox[t * 4 + 3] * f;
    }
}

extern "C" void kernel_launch(void* const* d_in, const int* in_sizes, int n_in,
                              void* d_out, int out_size) {
    const float* loc    = (const float*)d_in[0];
    const float* conf   = (const float*)d_in[1];
    const float* priors = (const float*)d_in[2];
    float* out = (float*)d_out;

    k_zero<<<(BATCH * BINS + 255) / 256, 256>>>();
    k_keys_hist<<<dim3(32, BATCH), 256>>>(conf);
    k_thresh<<<BATCH, 256>>>();
    k_collect<<<dim3(32, BATCH), 256>>>(conf);
    k_final<<<BATCH, 512>>>(loc, priors, out);
}

// round 5
// speedup vs baseline: 1.0035x; 1.0035x over previous
#include <cuda_runtime.h>
#include <math.h>

#define BATCH 32
#define P 250000
#define TOPK 200
#define BINS 4096
#define CAP 4096
#define NMS_THR 0.45f
#define CONF_THR 0.01f

#define CHUNKS (P / 8)   // 31250 exactly, no tail

// ---------------- scratch (device globals: no allocation allowed) ----------------
__device__ unsigned short     g_key16[(size_t)BATCH * P];   // 16 MB (d-key top bits)
__device__ unsigned int       g_hist[BATCH * BINS];
__device__ int                g_thresh[BATCH];
__device__ int                g_count[BATCH];
__device__ unsigned long long g_cand[BATCH * CAP];

// sortable key for d (possibly negative): larger float -> larger uint
__device__ __forceinline__ unsigned f2key(float f) {
    unsigned b = __float_as_uint(f);
    return (b & 0x80000000u) ? ~b : (b | 0x80000000u);
}

// Replicate XLA softmax(conf)[:,1] rounding exactly
__device__ __forceinline__ float xla_score(float c0, float c1) {
    if (c1 >= c0) {
        float e0 = expf(__fsub_rn(c0, c1));
        return __fdiv_rn(1.0f, __fadd_rn(e0, 1.0f));
    } else {
        float e1 = expf(__fsub_rn(c1, c0));
        return __fdiv_rn(e1, __fadd_rn(1.0f, e1));
    }
}

// ---------------- K0: zero hist + counters ----------------
__global__ void k_zero() {
    int i = blockIdx.x * blockDim.x + threadIdx.x;
    if (i < BATCH * BINS) g_hist[i] = 0u;
    if (i < BATCH)        g_count[i] = 0;
}

// ---------------- K1: stream conf (float4 x4), write packed keys (uint4), histogram ----------------
__global__ void k_keys_hist(const float* __restrict__ conf) {
    const int b = blockIdx.y;
    __shared__ unsigned int sh[BINS];
    for (int i = threadIdx.x; i < BINS; i += blockDim.x) sh[i] = 0u;
    __syncthreads();

    const float4* cp4  = (const float4*)(conf + (size_t)b * P * 2);   // 2 pairs per float4
    uint4*        kout = (uint4*)(g_key16 + (size_t)b * P);           // 8 keys per uint4
    const int stride = gridDim.x * blockDim.x;

    for (int c = blockIdx.x * blockDim.x + threadIdx.x; c < CHUNKS; c += stride) {
        float4 v0 = cp4[c * 4 + 0];
        float4 v1 = cp4[c * 4 + 1];
        float4 v2 = cp4[c * 4 + 2];
        float4 v3 = cp4[c * 4 + 3];
        unsigned k0 = f2key(__fsub_rn(v0.y, v0.x));
        unsigned k1 = f2key(__fsub_rn(v0.w, v0.z));
        unsigned k2 = f2key(__fsub_rn(v1.y, v1.x));
        unsigned k3 = f2key(__fsub_rn(v1.w, v1.z));
        unsigned k4 = f2key(__fsub_rn(v2.y, v2.x));
        unsigned k5 = f2key(__fsub_rn(v2.w, v2.z));
        unsigned k6 = f2key(__fsub_rn(v3.y, v3.x));
        unsigned k7 = f2key(__fsub_rn(v3.w, v3.z));

        uint4 o;
        o.x = (k0 >> 16) | (k1 & 0xFFFF0000u);
        o.y = (k2 >> 16) | (k3 & 0xFFFF0000u);
        o.z = (k4 >> 16) | (k5 & 0xFFFF0000u);
        o.w = (k6 >> 16) | (k7 & 0xFFFF0000u);
        kout[c] = o;

        atomicAdd(&sh[k0 >> 20], 1u);
        atomicAdd(&sh[k1 >> 20], 1u);
        atomicAdd(&sh[k2 >> 20], 1u);
        atomicAdd(&sh[k3 >> 20], 1u);
        atomicAdd(&sh[k4 >> 20], 1u);
        atomicAdd(&sh[k5 >> 20], 1u);
        atomicAdd(&sh[k6 >> 20], 1u);
        atomicAdd(&sh[k7 >> 20], 1u);
    }
    __syncthreads();
    for (int i = threadIdx.x; i < BINS; i += blockDim.x) {
        unsigned v = sh[i];
        if (v) atomicAdd(&g_hist[b * BINS + i], v);
    }
}

// ---------------- K2: per-batch threshold bin ----------------
__global__ void k_thresh() {
    const int b = blockIdx.x;
    __shared__ unsigned sh[BINS];
    __shared__ unsigned part[256];
    const int t = threadIdx.x;

    for (int i = t; i < BINS; i += 256) sh[i] = g_hist[b * BINS + i];
    __syncthreads();

    const int hi = BINS - 1 - t * 16;
    unsigned s = 0;
    #pragma unroll
    for (int j = 0; j < 16; j++) s += sh[hi - j];
    part[t] = s;
    __syncthreads();

    for (int off = 1; off < 256; off <<= 1) {
        unsigned v = (t >= off) ? part[t - off] : 0u;
        __syncthreads();
        part[t] += v;
        __syncthreads();
    }

    unsigned cum  = part[t];
    unsigned prev = (t == 0) ? 0u : part[t - 1];
    if (cum >= TOPK && prev < TOPK) {
        unsigned acc = prev;
        int bin = hi;
        #pragma unroll
        for (int j = 0; j < 16; j++) {
            acc += sh[hi - j];
            if (acc >= TOPK) { bin = hi - j; break; }
        }
        g_thresh[b] = bin;
    }
}

// ---------------- K3: scan packed keys (uint4), collect candidates with score key ----------------
__global__ void k_collect(const float* __restrict__ conf) {
    const int b = blockIdx.y;
    const unsigned th = (unsigned)g_thresh[b];
    const float2* cp  = (const float2*)(conf + (size_t)b * P * 2);
    const uint4*  kin = (const uint4*)(g_key16 + (size_t)b * P);
    const int stride = gridDim.x * blockDim.x;

    for (int c = blockIdx.x * blockDim.x + threadIdx.x; c < CHUNKS; c += stride) {
        uint4 kv = kin[c];
        unsigned w[4] = {kv.x, kv.y, kv.z, kv.w};
        #pragma unroll
        for (int q = 0; q < 4; q++) {
            #pragma unroll
            for (int h = 0; h < 2; h++) {
                unsigned k16 = (w[q] >> (h * 16)) & 0xFFFFu;
                if ((k16 >> 4) >= th) {
                    int i = c * 8 + q * 2 + h;
                    float2 cf = cp[i];
                    float scv = xla_score(cf.x, cf.y);
                    unsigned long long comp =
                        ((unsigned long long)__float_as_uint(scv) << 32) |
                        (unsigned long long)(0xFFFFFFFFu - (unsigned)i);
                    int pos = atomicAdd(&g_count[b], 1);
                    if (pos < CAP) g_cand[b * CAP + pos] = comp;
                }
            }
        }
    }
}

// ---------------- K4: sort, decode, NMS, write ----------------
__global__ __launch_bounds__(512) void k_final(const float* __restrict__ loc,
                                               const float* __restrict__ priors,
                                               float* __restrict__ out) {
    const int b = blockIdx.x;
    const int t = threadIdx.x;

    __shared__ unsigned long long sc[CAP];
    __shared__ float    sbox[TOPK * 4];
    __shared__ float    sscore[TOPK];
    __shared__ unsigned smask[TOPK * 7];
    __shared__ int      skeep[TOPK];

    int n = g_count[b];
    if (n > CAP) n = CAP;
    int m = 256;
    while (m < n) m <<= 1;

    for (int i = t; i < m; i += 512) sc[i] = (i < n) ? g_cand[b * CAP + i] : 0ull;
    __syncthreads();

    // bitonic sort descending on (score_bits, ~idx)
    for (int k2 = 2; k2 <= m; k2 <<= 1) {
        for (int j = k2 >> 1; j > 0; j >>= 1) {
            for (int i = t; i < m; i += 512) {
                int ixj = i ^ j;
                if (ixj > i) {
                    unsigned long long a = sc[i], c = sc[ixj];
                    bool sw = ((i & k2) == 0) ? (a < c) : (a > c);
                    if (sw) { sc[i] = c; sc[ixj] = a; }
                }
            }
            __syncthreads();
        }
    }

    // top-200: decode box + score
    if (t < TOPK) {
        unsigned long long c = sc[t];
        float score  = __uint_as_float((unsigned)(c >> 32));
        unsigned idx = 0xFFFFFFFFu - (unsigned)(c & 0xFFFFFFFFull);

        const float* l  = loc + ((size_t)b * P + idx) * 4;
        const float* pr = priors + (size_t)idx * 4;
        float px0 = pr[0], py0 = pr[1], px1 = pr[2], py1 = pr[3];
        float pw = px1 - px0, ph = py1 - py0;
        float pcx = (px0 + px1) * 0.5f, pcy = (py0 + py1) * 0.5f;
        float l0 = l[0], l1 = l[1], l2 = l[2], l3 = l[3];
        float cx = pcx + l0 * pw;
        float cy = pcy + l1 * ph;
        float w  = pw * expf(l2);
        float h  = ph * expf(l3);
        sbox[t * 4 + 0] = cx - w * 0.5f;
        sbox[t * 4 + 1] = cy - h * 0.5f;
        sbox[t * 4 + 2] = cx + w * 0.5f;
        sbox[t * 4 + 3] = cy + h * 0.5f;
        sscore[t] = score;
    }
    for (int i = t; i < TOPK * 7; i += 512) smask[i] = 0u;
    __syncthreads();

    // IoU suppression bitmask (j < i, iou > thr)
    for (int p = t; p < TOPK * TOPK; p += 512) {
        int i = p / TOPK, j = p % TOPK;
        if (j < i) {
            float ax0 = sbox[i * 4 + 0], ay0 = sbox[i * 4 + 1];
            float ax1 = sbox[i * 4 + 2], ay1 = sbox[i * 4 + 3];
            float bx0 = sbox[j * 4 + 0], by0 = sbox[j * 4 + 1];
            float bx1 = sbox[j * 4 + 2], by1 = sbox[j * 4 + 3];
            float iw = fminf(ax1, bx1) - fmaxf(ax0, bx0); iw = fmaxf(iw, 0.0f);
            float ih = fminf(ay1, by1) - fmaxf(ay0, by0); ih = fmaxf(ih, 0.0f);
            float inter = iw * ih;
            float aa = fmaxf(ax1 - ax0, 0.0f) * fmaxf(ay1 - ay0, 0.0f);
            float ab = fmaxf(bx1 - bx0, 0.0f) * fmaxf(by1 - by0, 0.0f);
            float uni = fmaxf(aa + ab - inter, 1e-9f);
            if (inter / uni > NMS_THR)
                atomicOr(&smask[i * 7 + (j >> 5)], 1u << (j & 31));
        }
    }
    __syncthreads();

    // greedy NMS on warp 0: lane w owns keep-bit word w (w < 7)
    if (t < 32) {
        unsigned kw = 0u;
        for (int i = 0; i < TOPK; i++) {
            bool sup = (t < 7) && ((smask[i * 7 + t] & kw) != 0u);
            sup = __any_sync(0xffffffffu, sup);
            bool kp = (sscore[i] > CONF_THR) && !sup;
            if (t == (i >> 5) && kp) kw |= 1u << (i & 31);
            if (t == 0) skeep[i] = kp ? 1 : 0;
        }
    }
    __syncthreads();

    // write output [B,2,TOPK,5]
    float* ob = out + (size_t)b * 2 * TOPK * 5;
    for (int i = t; i < TOPK * 5; i += 512) ob[i] = 0.0f;
    if (t < TOPK) {
        float f = skeep[t] ? 1.0f : 0.0f;
        float* r = ob + TOPK * 5 + t * 5;
        r[0] = sscore[t] * f;
        r[1] = sbox[t * 4 + 0] * f;
        r[2] = sbox[t * 4 + 1] * f;
        r[3] = sbox[t * 4 + 2] * f;
        r[4] = sbox[t * 4 + 3] * f;
    }
}

extern "C" void kernel_launch(void* const* d_in, const int* in_sizes, int n_in,
                              void* d_out, int out_size) {
    const float* loc    = (const float*)d_in[0];
    const float* conf   = (const float*)d_in[1];
    const float* priors = (const float*)d_in[2];
    float* out = (float*)d_out;

    k_zero<<<(BATCH * BINS + 255) / 256, 256>>>();
    k_keys_hist<<<dim3(16, BATCH), 256>>>(conf);
    k_thresh<<<BATCH, 256>>>();
    k_collect<<<dim3(16, BATCH), 256>>>(conf);
    k_final<<<BATCH, 512>>>(loc, priors, out);
}

// round 9
// speedup vs baseline: 1.3279x; 1.3232x over previous
#include <cuda_runtime.h>
#include <math.h>

#define BATCH 32
#define P 250000
#define TOPK 200
#define BINS 4096
#define CAP 4096
#define NMS_THR 0.45f
#define CONF_THR 0.01f
#define SIEVE_D 4.0f
#define CHUNKS (P / 8)   // 31250 exactly

// ---------------- scratch (device globals) ----------------
__device__ unsigned int       g_hist[BATCH * BINS];   // fallback only
__device__ int                g_count[BATCH * 32];    // padded: use [b*32]
__device__ int                g_thresh[BATCH];        // -1 => primary path valid
__device__ unsigned long long g_cand[BATCH * CAP];

// sortable key for d: larger float -> larger uint
__device__ __forceinline__ unsigned f2key(float f) {
    unsigned b = __float_as_uint(f);
    return (b & 0x80000000u) ? ~b : (b | 0x80000000u);
}

// Replicate XLA softmax(conf)[:,1] rounding exactly
__device__ __forceinline__ float xla_score(float c0, float c1) {
    if (c1 >= c0) {
        float e0 = expf(__fsub_rn(c0, c1));
        return __fdiv_rn(1.0f, __fadd_rn(e0, 1.0f));
    } else {
        float e1 = expf(__fsub_rn(c1, c0));
        return __fdiv_rn(e1, __fadd_rn(1.0f, e1));
    }
}

__device__ __forceinline__ void sieve_push(int b, int i, float c0, float c1) {
    if (__fsub_rn(c1, c0) > SIEVE_D) {
        float s = xla_score(c0, c1);
        unsigned long long comp =
            ((unsigned long long)__float_as_uint(s) << 32) |
            (unsigned long long)(0xFFFFFFFFu - (unsigned)i);  // score desc, idx asc on tie
        int pos = atomicAdd(&g_count[b * 32], 1);
        if (pos < CAP) g_cand[b * CAP + pos] = comp;
    }
}

// ---------------- K0: zero counters + fallback hist ----------------
__global__ void k_zero() {
    int i = blockIdx.x * blockDim.x + threadIdx.x;
    if (i < BATCH * BINS) g_hist[i] = 0u;
    if (i < BATCH)        g_count[i * 32] = 0;
}

// ---------------- K1 (primary): single pass over conf, static sieve ----------------
__global__ void k_sieve(const float* __restrict__ conf) {
    const int b = blockIdx.y;
    const float4* cp4 = (const float4*)(conf + (size_t)b * P * 2);  // 2 pairs / float4
    const int stride = gridDim.x * blockDim.x;

    for (int c = blockIdx.x * blockDim.x + threadIdx.x; c < CHUNKS; c += stride) {
        float4 v0 = cp4[c * 4 + 0];
        float4 v1 = cp4[c * 4 + 1];
        float4 v2 = cp4[c * 4 + 2];
        float4 v3 = cp4[c * 4 + 3];
        int base = c * 8;
        sieve_push(b, base + 0, v0.x, v0.y);
        sieve_push(b, base + 1, v0.z, v0.w);
        sieve_push(b, base + 2, v1.x, v1.y);
        sieve_push(b, base + 3, v1.z, v1.w);
        sieve_push(b, base + 4, v2.x, v2.y);
        sieve_push(b, base + 5, v2.z, v2.w);
        sieve_push(b, base + 6, v3.x, v3.y);
        sieve_push(b, base + 7, v3.z, v3.w);
    }
}

// ---------------- F1 (fallback): 12-bit histogram from conf (early-exit when valid) ----------------
__global__ void f_hist(const float* __restrict__ conf) {
    const int b = blockIdx.y;
    int cnt = g_count[b * 32];
    if (cnt >= TOPK && cnt <= CAP) return;   // uniform per block

    __shared__ unsigned sh[BINS];
    for (int i = threadIdx.x; i < BINS; i += blockDim.x) sh[i] = 0u;
    __syncthreads();

    const float2* cp = (const float2*)(conf + (size_t)b * P * 2);
    const int stride = gridDim.x * blockDim.x;
    for (int i = blockIdx.x * blockDim.x + threadIdx.x; i < P; i += stride) {
        float2 c = cp[i];
        unsigned key = f2key(__fsub_rn(c.y, c.x));
        atomicAdd(&sh[key >> 20], 1u);
    }
    __syncthreads();
    for (int i = threadIdx.x; i < BINS; i += blockDim.x) {
        unsigned v = sh[i];
        if (v) atomicAdd(&g_hist[b * BINS + i], v);
    }
}

// ---------------- F2 (fallback): threshold bin; also resets counter ----------------
__global__ void f_thresh() {
    const int b = blockIdx.x;
    const int t = threadIdx.x;
    int cnt = g_count[b * 32];
    if (cnt >= TOPK && cnt <= CAP) {
        if (t == 0) g_thresh[b] = -1;        // primary valid
        return;
    }
    if (t == 0) g_count[b * 32] = 0;         // f_collect refills

    __shared__ unsigned sh[BINS];
    __shared__ unsigned part[256];

    for (int i = t; i < BINS; i += 256) sh[i] = g_hist[b * BINS + i];
    __syncthreads();

    const int hi = BINS - 1 - t * 16;
    unsigned s = 0;
    #pragma unroll
    for (int j = 0; j < 16; j++) s += sh[hi - j];
    part[t] = s;
    __syncthreads();

    for (int off = 1; off < 256; off <<= 1) {
        unsigned v = (t >= off) ? part[t - off] : 0u;
        __syncthreads();
        part[t] += v;
        __syncthreads();
    }

    unsigned cum  = part[t];
    unsigned prev = (t == 0) ? 0u : part[t - 1];
    if (cum >= TOPK && prev < TOPK) {
        unsigned acc = prev;
        int bin = hi;
        #pragma unroll
        for (int j = 0; j < 16; j++) {
            acc += sh[hi - j];
            if (acc >= TOPK) { bin = hi - j; break; }
        }
        g_thresh[b] = bin;
    }
}

// ---------------- F3 (fallback): collect candidates above threshold bin ----------------
__global__ void f_collect(const float* __restrict__ conf) {
    const int b = blockIdx.y;
    const int th = g_thresh[b];
    if (th < 0) return;                       // primary valid

    const float2* cp = (const float2*)(conf + (size_t)b * P * 2);
    const int stride = gridDim.x * blockDim.x;
    for (int i = blockIdx.x * blockDim.x + threadIdx.x; i < P; i += stride) {
        float2 c = cp[i];
        unsigned key = f2key(__fsub_rn(c.y, c.x));
        if ((int)(key >> 20) >= th) {
            float s = xla_score(c.x, c.y);
            unsigned long long comp =
                ((unsigned long long)__float_as_uint(s) << 32) |
                (unsigned long long)(0xFFFFFFFFu - (unsigned)i);
            int pos = atomicAdd(&g_count[b * 32], 1);
            if (pos < CAP) g_cand[b * CAP + pos] = comp;
        }
    }
}

// ---------------- K4: sort, decode, NMS, write ----------------
__global__ __launch_bounds__(512) void k_final(const float* __restrict__ loc,
                                               const float* __restrict__ priors,
                                               float* __restrict__ out) {
    const int b = blockIdx.x;
    const int t = threadIdx.x;

    __shared__ unsigned long long sc[CAP];
    __shared__ float    sbox[TOPK * 4];
    __shared__ float    sscore[TOPK];
    __shared__ unsigned smask[TOPK * 7];
    __shared__ int      skeep[TOPK];

    int n = g_count[b * 32];
    if (n > CAP) n = CAP;
    int m = 256;
    while (m < n) m <<= 1;

    for (int i = t; i < m; i += 512) sc[i] = (i < n) ? g_cand[b * CAP + i] : 0ull;
    __syncthreads();

    // bitonic sort descending on (score_bits, ~idx)
    for (int k2 = 2; k2 <= m; k2 <<= 1) {
        for (int j = k2 >> 1; j > 0; j >>= 1) {
            for (int i = t; i < m; i += 512) {
                int ixj = i ^ j;
                if (ixj > i) {
                    unsigned long long a = sc[i], c = sc[ixj];
                    bool sw = ((i & k2) == 0) ? (a < c) : (a > c);
                    if (sw) { sc[i] = c; sc[ixj] = a; }
                }
            }
            __syncthreads();
        }
    }

    // top-200: decode box + score
    if (t < TOPK) {
        unsigned long long c = sc[t];
        float score  = __uint_as_float((unsigned)(c >> 32));
        unsigned idx = 0xFFFFFFFFu - (unsigned)(c & 0xFFFFFFFFull);

        const float* l  = loc + ((size_t)b * P + idx) * 4;
        const float* pr = priors + (size_t)idx * 4;
        float px0 = pr[0], py0 = pr[1], px1 = pr[2], py1 = pr[3];
        float pw = px1 - px0, ph = py1 - py0;
        float pcx = (px0 + px1) * 0.5f, pcy = (py0 + py1) * 0.5f;
        float l0 = l[0], l1 = l[1], l2 = l[2], l3 = l[3];
        float cx = pcx + l0 * pw;
        float cy = pcy + l1 * ph;
        float w  = pw * expf(l2);
        float h  = ph * expf(l3);
        sbox[t * 4 + 0] = cx - w * 0.5f;
        sbox[t * 4 + 1] = cy - h * 0.5f;
        sbox[t * 4 + 2] = cx + w * 0.5f;
        sbox[t * 4 + 3] = cy + h * 0.5f;
        sscore[t] = score;
    }
    for (int i = t; i < TOPK * 7; i += 512) smask[i] = 0u;
    __syncthreads();

    // IoU suppression bitmask (j < i, iou > thr)
    for (int p = t; p < TOPK * TOPK; p += 512) {
        int i = p / TOPK, j = p % TOPK;
        if (j < i) {
            float ax0 = sbox[i * 4 + 0], ay0 = sbox[i * 4 + 1];
            float ax1 = sbox[i * 4 + 2], ay1 = sbox[i * 4 + 3];
            float bx0 = sbox[j * 4 + 0], by0 = sbox[j * 4 + 1];
            float bx1 = sbox[j * 4 + 2], by1 = sbox[j * 4 + 3];
            float iw = fminf(ax1, bx1) - fmaxf(ax0, bx0); iw = fmaxf(iw, 0.0f);
            float ih = fminf(ay1, by1) - fmaxf(ay0, by0); ih = fmaxf(ih, 0.0f);
            float inter = iw * ih;
            float aa = fmaxf(ax1 - ax0, 0.0f) * fmaxf(ay1 - ay0, 0.0f);
            float ab = fmaxf(bx1 - bx0, 0.0f) * fmaxf(by1 - by0, 0.0f);
            float uni = fmaxf(aa + ab - inter, 1e-9f);
            if (inter / uni > NMS_THR)
                atomicOr(&smask[i * 7 + (j >> 5)], 1u << (j & 31));
        }
    }
    __syncthreads();

    // greedy NMS on warp 0: lane w owns keep-bit word w (w < 7)
    if (t < 32) {
        unsigned kw = 0u;
        for (int i = 0; i < TOPK; i++) {
            bool sup = (t < 7) && ((smask[i * 7 + t] & kw) != 0u);
            sup = __any_sync(0xffffffffu, sup);
            bool kp = (sscore[i] > CONF_THR) && !sup;
            if (t == (i >> 5) && kp) kw |= 1u << (i & 31);
            if (t == 0) skeep[i] = kp ? 1 : 0;
        }
    }
    __syncthreads();

    // write output [B,2,TOPK,5]
    float* ob = out + (size_t)b * 2 * TOPK * 5;
    for (int i = t; i < TOPK * 5; i += 512) ob[i] = 0.0f;
    if (t < TOPK) {
        float f = skeep[t] ? 1.0f : 0.0f;
        float* r = ob + TOPK * 5 + t * 5;
        r[0] = sscore[t] * f;
        r[1] = sbox[t * 4 + 0] * f;
        r[2] = sbox[t * 4 + 1] * f;
        r[3] = sbox[t * 4 + 2] * f;
        r[4] = sbox[t * 4 + 3] * f;
    }
}

extern "C" void kernel_launch(void* const* d_in, const int* in_sizes, int n_in,
                              void* d_out, int out_size) {
    const float* loc    = (const float*)d_in[0];
    const float* conf   = (const float*)d_in[1];
    const float* priors = (const float*)d_in[2];
    float* out = (float*)d_out;

    k_zero<<<(BATCH * BINS + 255) / 256, 256>>>();
    k_sieve<<<dim3(32, BATCH), 256>>>(conf);
    f_hist<<<dim3(16, BATCH), 256>>>(conf);      // early-exit when sieve valid
    f_thresh<<<BATCH, 256>>>();                  // sets g_thresh = -1 when valid
    f_collect<<<dim3(16, BATCH), 256>>>(conf);   // early-exit when valid
    k_final<<<BATCH, 512>>>(loc, priors, out);
}

// round 11
// speedup vs baseline: 1.4749x; 1.1107x over previous
#include <cuda_runtime.h>
#include <math.h>

#define BATCH 32
#define P 250000
#define TOPK 200
#define BINS 4096
#define CAP 4096
#define NMS_THR 0.45f
#define CONF_THR 0.01f
#define SIEVE_D 4.0f
#define CHUNKS (P / 8)   // 31250 exactly

// ---------------- scratch (device globals; BSS-zeroed at load) ----------------
__device__ int                g_count[BATCH * 32];    // padded: use [b*32]; reset by k_final
__device__ unsigned long long g_cand[BATCH * CAP];

// sortable key for d: larger float -> larger uint
__device__ __forceinline__ unsigned f2key(float f) {
    unsigned b = __float_as_uint(f);
    return (b & 0x80000000u) ? ~b : (b | 0x80000000u);
}

// Replicate XLA softmax(conf)[:,1] rounding exactly
__device__ __forceinline__ float xla_score(float c0, float c1) {
    if (c1 >= c0) {
        float e0 = expf(__fsub_rn(c0, c1));
        return __fdiv_rn(1.0f, __fadd_rn(e0, 1.0f));
    } else {
        float e1 = expf(__fsub_rn(c1, c0));
        return __fdiv_rn(e1, __fadd_rn(1.0f, e1));
    }
}

__device__ __forceinline__ void sieve_push(int b, int i, float c0, float c1) {
    if (__fsub_rn(c1, c0) > SIEVE_D) {
        float s = xla_score(c0, c1);
        unsigned long long comp =
            ((unsigned long long)__float_as_uint(s) << 32) |
            (unsigned long long)(0xFFFFFFFFu - (unsigned)i);  // score desc, idx asc on tie
        int pos = atomicAdd(&g_count[b * 32], 1);
        if (pos < CAP) g_cand[b * CAP + pos] = comp;
    }
}

// ---------------- K1: single pass over conf, static sieve ----------------
__global__ void k_sieve(const float* __restrict__ conf) {
    const int b = blockIdx.y;
    const float4* cp4 = (const float4*)(conf + (size_t)b * P * 2);  // 2 pairs / float4
    const int stride = gridDim.x * blockDim.x;

    for (int c = blockIdx.x * blockDim.x + threadIdx.x; c < CHUNKS; c += stride) {
        float4 v0 = cp4[c * 4 + 0];
        float4 v1 = cp4[c * 4 + 1];
        float4 v2 = cp4[c * 4 + 2];
        float4 v3 = cp4[c * 4 + 3];
        int base = c * 8;
        sieve_push(b, base + 0, v0.x, v0.y);
        sieve_push(b, base + 1, v0.z, v0.w);
        sieve_push(b, base + 2, v1.x, v1.y);
        sieve_push(b, base + 3, v1.z, v1.w);
        sieve_push(b, base + 4, v2.x, v2.y);
        sieve_push(b, base + 5, v2.z, v2.w);
        sieve_push(b, base + 6, v3.x, v3.y);
        sieve_push(b, base + 7, v3.z, v3.w);
    }
}

// ---------------- K2: (inline fallback) + sort + decode + NMS + write ----------------
__global__ __launch_bounds__(512) void k_final(const float* __restrict__ loc,
                                               const float* __restrict__ priors,
                                               const float* __restrict__ conf,
                                               float* __restrict__ out) {
    const int b = blockIdx.x;
    const int t = threadIdx.x;

    __shared__ union {
        unsigned long long sc[CAP];    // sort buffer (32 KB)
        unsigned           hist[BINS]; // fallback histogram (16 KB, overlaid)
    } u;
    __shared__ float    sbox[TOPK * 4];
    __shared__ float    sscore[TOPK];
    __shared__ unsigned smask[TOPK * 7];
    __shared__ int      skeep[TOPK];
    __shared__ unsigned part[512];
    __shared__ int      s_th, s_n;

    int n = g_count[b * 32];

    if (n >= TOPK && n <= CAP) {
        // ---- primary: candidates already in g_cand ----
        for (int i = t; i < n; i += 512) u.sc[i] = g_cand[b * CAP + i];
    } else {
        // ---- fallback: full per-batch histogram top-k (rarely taken) ----
        const float2* cp = (const float2*)(conf + (size_t)b * P * 2);

        for (int i = t; i < BINS; i += 512) u.hist[i] = 0u;
        __syncthreads();
        for (int i = t; i < P; i += 512) {
            float2 c = cp[i];
            atomicAdd(&u.hist[f2key(__fsub_rn(c.y, c.x)) >> 20], 1u);
        }
        __syncthreads();

        // partial sums of 8-bin chunks from the top
        const int hi = BINS - 1 - t * 8;
        unsigned s = 0;
        #pragma unroll
        for (int j = 0; j < 8; j++) s += u.hist[hi - j];
        part[t] = s;
        __syncthreads();

        if (t == 0) {
            unsigned acc = 0; int th = 0;
            for (int q = 0; q < 512; q++) {
                if (acc + part[q] >= TOPK) {
                    int h2 = BINS - 1 - q * 8;
                    for (int j = 0; j < 8; j++) {
                        acc += u.hist[h2 - j];
                        if (acc >= TOPK) { th = h2 - j; break; }
                    }
                    break;
                }
                acc += part[q];
            }
            s_th = th;
            s_n  = 0;
        }
        __syncthreads();
        const int th = s_th;
        __syncthreads();   // all reads of u.hist done before overwriting with u.sc

        for (int i = t; i < P; i += 512) {
            float2 c = cp[i];
            unsigned key = f2key(__fsub_rn(c.y, c.x));
            if ((int)(key >> 20) >= th) {
                float sv = xla_score(c.x, c.y);
                unsigned long long comp =
                    ((unsigned long long)__float_as_uint(sv) << 32) |
                    (unsigned long long)(0xFFFFFFFFu - (unsigned)i);
                int pos = atomicAdd(&s_n, 1);
                if (pos < CAP) u.sc[pos] = comp;
            }
        }
        __syncthreads();
        n = s_n;
        if (n > CAP) n = CAP;
    }

    int m = 256;
    while (m < n) m <<= 1;
    for (int i = t; i < m; i += 512) if (i >= n) u.sc[i] = 0ull;
    __syncthreads();

    // bitonic sort descending on (score_bits, ~idx)
    for (int k2 = 2; k2 <= m; k2 <<= 1) {
        for (int j = k2 >> 1; j > 0; j >>= 1) {
            for (int i = t; i < m; i += 512) {
                int ixj = i ^ j;
                if (ixj > i) {
                    unsigned long long a = u.sc[i], c = u.sc[ixj];
                    bool sw = ((i & k2) == 0) ? (a < c) : (a > c);
                    if (sw) { u.sc[i] = c; u.sc[ixj] = a; }
                }
            }
            __syncthreads();
        }
    }

    // top-200: decode box + score
    if (t < TOPK) {
        unsigned long long c = u.sc[t];
        float score  = __uint_as_float((unsigned)(c >> 32));
        unsigned idx = 0xFFFFFFFFu - (unsigned)(c & 0xFFFFFFFFull);

        const float* l  = loc + ((size_t)b * P + idx) * 4;
        const float* pr = priors + (size_t)idx * 4;
        float px0 = pr[0], py0 = pr[1], px1 = pr[2], py1 = pr[3];
        float pw = px1 - px0, ph = py1 - py0;
        float pcx = (px0 + px1) * 0.5f, pcy = (py0 + py1) * 0.5f;
        float l0 = l[0], l1 = l[1], l2 = l[2], l3 = l[3];
        float cx = pcx + l0 * pw;
        float cy = pcy + l1 * ph;
        float w  = pw * expf(l2);
        float h  = ph * expf(l3);
        sbox[t * 4 + 0] = cx - w * 0.5f;
        sbox[t * 4 + 1] = cy - h * 0.5f;
        sbox[t * 4 + 2] = cx + w * 0.5f;
        sbox[t * 4 + 3] = cy + h * 0.5f;
        sscore[t] = score;
    }
    for (int i = t; i < TOPK * 7; i += 512) smask[i] = 0u;
    __syncthreads();

    // IoU suppression bitmask (j < i, iou > thr)
    for (int p = t; p < TOPK * TOPK; p += 512) {
        int i = p / TOPK, j = p % TOPK;
        if (j < i) {
            float ax0 = sbox[i * 4 + 0], ay0 = sbox[i * 4 + 1];
            float ax1 = sbox[i * 4 + 2], ay1 = sbox[i * 4 + 3];
            float bx0 = sbox[j * 4 + 0], by0 = sbox[j * 4 + 1];
            float bx1 = sbox[j * 4 + 2], by1 = sbox[j * 4 + 3];
            float iw = fminf(ax1, bx1) - fmaxf(ax0, bx0); iw = fmaxf(iw, 0.0f);
            float ih = fminf(ay1, by1) - fmaxf(ay0, by0); ih = fmaxf(ih, 0.0f);
            float inter = iw * ih;
            float aa = fmaxf(ax1 - ax0, 0.0f) * fmaxf(ay1 - ay0, 0.0f);
            float ab = fmaxf(bx1 - bx0, 0.0f) * fmaxf(by1 - by0, 0.0f);
            float uni = fmaxf(aa + ab - inter, 1e-9f);
            if (inter / uni > NMS_THR)
                atomicOr(&smask[i * 7 + (j >> 5)], 1u << (j & 31));
        }
    }
    __syncthreads();

    // greedy NMS on warp 0: lane w owns keep-bit word w (w < 7)
    if (t < 32) {
        unsigned kw = 0u;
        for (int i = 0; i < TOPK; i++) {
            bool sup = (t < 7) && ((smask[i * 7 + t] & kw) != 0u);
            sup = __any_sync(0xffffffffu, sup);
            bool kp = (sscore[i] > CONF_THR) && !sup;
            if (t == (i >> 5) && kp) kw |= 1u << (i & 31);
            if (t == 0) skeep[i] = kp ? 1 : 0;
        }
    }
    __syncthreads();

    // write output [B,2,TOPK,5]; class 0 stays zero
    float* ob = out + (size_t)b * 2 * TOPK * 5;
    for (int i = t; i < TOPK * 5; i += 512) ob[i] = 0.0f;
    if (t < TOPK) {
        float f = skeep[t] ? 1.0f : 0.0f;
        float* r = ob + TOPK * 5 + t * 5;
        r[0] = sscore[t] * f;
        r[1] = sbox[t * 4 + 0] * f;
        r[2] = sbox[t * 4 + 1] * f;
        r[3] = sbox[t * 4 + 2] * f;
        r[4] = sbox[t * 4 + 3] * f;
    }

    // reset counter for next graph replay (restores BSS-zero invariant)
    if (t == 0) g_count[b * 32] = 0;
}

extern "C" void kernel_launch(void* const* d_in, const int* in_sizes, int n_in,
                              void* d_out, int out_size) {
    const float* loc    = (const float*)d_in[0];
    const float* conf   = (const float*)d_in[1];
    const float* priors = (const float*)d_in[2];
    float* out = (float*)d_out;

    k_sieve<<<dim3(32, BATCH), 256>>>(conf);
    k_final<<<BATCH, 512>>>(loc, priors, conf, out);
}

// round 15
// speedup vs baseline: 1.5510x; 1.0516x over previous
#include <cuda_runtime.h>
#include <math.h>

#define BATCH 32
#define P 250000
#define TOPK 200
#define BINS 4096
#define CAP 4096
#define NMS_THR 0.45f
#define CONF_THR 0.01f
#define SIEVE_D 4.0f
#define NF4 (P / 2)          // 125000 float4 per batch slice (2 priors per float4)
#define NTHR 1024

// sortable key for d: larger float -> larger uint
__device__ __forceinline__ unsigned f2key(float f) {
    unsigned b = __float_as_uint(f);
    return (b & 0x80000000u) ? ~b : (b | 0x80000000u);
}

// Replicate XLA softmax(conf)[:,1] rounding exactly
__device__ __forceinline__ float xla_score(float c0, float c1) {
    if (c1 >= c0) {
        float e0 = expf(__fsub_rn(c0, c1));
        return __fdiv_rn(1.0f, __fadd_rn(e0, 1.0f));
    } else {
        float e1 = expf(__fsub_rn(c1, c0));
        return __fdiv_rn(e1, __fadd_rn(1.0f, e1));
    }
}

__device__ __forceinline__ unsigned long long make_key(int i, float c0, float c1) {
    float s = xla_score(c0, c1);
    return ((unsigned long long)__float_as_uint(s) << 32) |
           (unsigned long long)(0xFFFFFFFFu - (unsigned)i);   // score desc, idx asc on tie
}

// ---------------- single fused kernel: one block per batch ----------------
__global__ __launch_bounds__(NTHR, 1) void k_all(const float* __restrict__ loc,
                                                 const float* __restrict__ priors,
                                                 const float* __restrict__ conf,
                                                 float* __restrict__ out) {
    const int b = blockIdx.x;
    const int t = threadIdx.x;

    __shared__ union {
        unsigned long long sc[CAP];    // candidate/sort buffer (32 KB)
        unsigned           hist[BINS]; // fallback histogram (16 KB, overlaid)
    } u;
    __shared__ float    sbox[TOPK * 4];
    __shared__ float    sscore[TOPK];
    __shared__ unsigned smask[TOPK * 7];
    __shared__ int      skeep[TOPK];
    __shared__ unsigned part[NTHR];
    __shared__ int      s_n, s_th;

    if (t == 0) s_n = 0;
    __syncthreads();

    // ---- Phase 1: stream conf slice, static sieve (d > SIEVE_D) into shared ----
    const float4* cp4 = (const float4*)(conf + (size_t)b * P * 2);
    for (int base = 0; base < NF4; base += NTHR * 8) {
        float4 v[8];
        int    idx[8];
        bool   ok[8];
        #pragma unroll
        for (int k = 0; k < 8; k++) {
            idx[k] = base + k * NTHR + t;
            ok[k]  = idx[k] < NF4;
            if (ok[k]) v[k] = cp4[idx[k]];
        }
        #pragma unroll
        for (int k = 0; k < 8; k++) {
            if (ok[k]) {
                if (__fsub_rn(v[k].y, v[k].x) > SIEVE_D) {
                    int pos = atomicAdd(&s_n, 1);
                    if (pos < CAP) u.sc[pos] = make_key(idx[k] * 2, v[k].x, v[k].y);
                }
                if (__fsub_rn(v[k].w, v[k].z) > SIEVE_D) {
                    int pos = atomicAdd(&s_n, 1);
                    if (pos < CAP) u.sc[pos] = make_key(idx[k] * 2 + 1, v[k].z, v[k].w);
                }
            }
        }
    }
    __syncthreads();
    int n = s_n;

    if (!(n >= TOPK && n <= CAP)) {
        // ---- Fallback: in-block histogram top-k (insurance; uniform branch) ----
        const float2* cp2 = (const float2*)(conf + (size_t)b * P * 2);

        for (int i = t; i < BINS; i += NTHR) u.hist[i] = 0u;
        __syncthreads();
        for (int i = t; i < P; i += NTHR) {
            float2 c = cp2[i];
            atomicAdd(&u.hist[f2key(__fsub_rn(c.y, c.x)) >> 20], 1u);
        }
        __syncthreads();

        const int hi = BINS - 1 - t * 4;
        unsigned s4 = 0;
        if (t * 4 < BINS) {
            #pragma unroll
            for (int j = 0; j < 4; j++) s4 += u.hist[hi - j];
        }
        part[t] = s4;
        __syncthreads();

        if (t == 0) {
            unsigned acc = 0; int th = 0;
            for (int q = 0; q < NTHR; q++) {
                if (acc + part[q] >= TOPK) {
                    int h2 = BINS - 1 - q * 4;
                    for (int j = 0; j < 4; j++) {
                        acc += u.hist[h2 - j];
                        if (acc >= TOPK) { th = h2 - j; break; }
                    }
                    break;
                }
                acc += part[q];
            }
            s_th = th;
            s_n  = 0;
        }
        __syncthreads();
        const int th = s_th;
        __syncthreads();   // hist reads complete before u.sc overwrite

        for (int i = t; i < P; i += NTHR) {
            float2 c = cp2[i];
            unsigned key = f2key(__fsub_rn(c.y, c.x));
            if ((int)(key >> 20) >= th) {
                int pos = atomicAdd(&s_n, 1);
                if (pos < CAP) u.sc[pos] = make_key(i, c.x, c.y);
            }
        }
        __syncthreads();
        n = s_n;
        if (n > CAP) n = CAP;
    }

    // ---- Phase 2: bitonic sort descending on (score_bits, ~idx) ----
    int m = 256;
    while (m < n) m <<= 1;
    for (int i = t; i < m; i += NTHR) if (i >= n) u.sc[i] = 0ull;
    __syncthreads();

    for (int k2 = 2; k2 <= m; k2 <<= 1) {
        for (int j = k2 >> 1; j > 0; j >>= 1) {
            for (int i = t; i < m; i += NTHR) {
                int ixj = i ^ j;
                if (ixj > i) {
                    unsigned long long a = u.sc[i], c = u.sc[ixj];
                    bool sw = ((i & k2) == 0) ? (a < c) : (a > c);
                    if (sw) { u.sc[i] = c; u.sc[ixj] = a; }
                }
            }
            __syncthreads();
        }
    }

    // ---- Phase 3: decode top-200 ----
    if (t < TOPK) {
        unsigned long long c = u.sc[t];
        float score  = __uint_as_float((unsigned)(c >> 32));
        unsigned idx = 0xFFFFFFFFu - (unsigned)(c & 0xFFFFFFFFull);

        const float* l  = loc + ((size_t)b * P + idx) * 4;
        const float* pr = priors + (size_t)idx * 4;
        float px0 = pr[0], py0 = pr[1], px1 = pr[2], py1 = pr[3];
        float pw = px1 - px0, ph = py1 - py0;
        float pcx = (px0 + px1) * 0.5f, pcy = (py0 + py1) * 0.5f;
        float l0 = l[0], l1 = l[1], l2 = l[2], l3 = l[3];
        float cx = pcx + l0 * pw;
        float cy = pcy + l1 * ph;
        float w  = pw * expf(l2);
        float h  = ph * expf(l3);
        sbox[t * 4 + 0] = cx - w * 0.5f;
        sbox[t * 4 + 1] = cy - h * 0.5f;
        sbox[t * 4 + 2] = cx + w * 0.5f;
        sbox[t * 4 + 3] = cy + h * 0.5f;
        sscore[t] = score;
    }
    for (int i = t; i < TOPK * 7; i += NTHR) smask[i] = 0u;
    __syncthreads();

    // ---- Phase 4: IoU suppression bitmask (j < i, iou > thr) ----
    for (int p = t; p < TOPK * TOPK; p += NTHR) {
        int i = p / TOPK, j = p % TOPK;
        if (j < i) {
            float ax0 = sbox[i * 4 + 0], ay0 = sbox[i * 4 + 1];
            float ax1 = sbox[i * 4 + 2], ay1 = sbox[i * 4 + 3];
            float bx0 = sbox[j * 4 + 0], by0 = sbox[j * 4 + 1];
            float bx1 = sbox[j * 4 + 2], by1 = sbox[j * 4 + 3];
            float iw = fminf(ax1, bx1) - fmaxf(ax0, bx0); iw = fmaxf(iw, 0.0f);
            float ih = fminf(ay1, by1) - fmaxf(ay0, by0); ih = fmaxf(ih, 0.0f);
            float inter = iw * ih;
            float aa = fmaxf(ax1 - ax0, 0.0f) * fmaxf(ay1 - ay0, 0.0f);
            float ab = fmaxf(bx1 - bx0, 0.0f) * fmaxf(by1 - by0, 0.0f);
            float uni = fmaxf(aa + ab - inter, 1e-9f);
            if (inter / uni > NMS_THR)
                atomicOr(&smask[i * 7 + (j >> 5)], 1u << (j & 31));
        }
    }
    __syncthreads();

    // ---- Phase 5: greedy NMS, blocked-ballot on warp 0 ----
    if (t < 32) {
        const unsigned lane = (unsigned)t;
        unsigned kwarr[7];
        #pragma unroll
        for (int g = 0; g < 7; g++) {
            int row = g * 32 + (int)lane;
            bool inrange = row < TOPK;
            unsigned mrow[7];
            #pragma unroll
            for (int w = 0; w < 7; w++) mrow[w] = inrange ? smask[row * 7 + w] : 0u;
            bool valid = inrange && (sscore[row] > CONF_THR);
            unsigned supext = 0u;
            for (int w = 0; w < g; w++) supext |= (mrow[w] & kwarr[w]);
            unsigned wg = mrow[g];
            unsigned kept = 0u;
            #pragma unroll
            for (int s = 0; s < 32; s++) {
                bool kp = (lane == (unsigned)s) && valid && (supext == 0u) &&
                          ((wg & kept) == 0u);
                kept |= __ballot_sync(0xffffffffu, kp);
            }
            kwarr[g] = kept;
            if (inrange) skeep[row] = (int)((kept >> lane) & 1u);
        }
    }
    __syncthreads();

    // ---- Phase 6: write output [B,2,TOPK,5]; class 0 stays zero ----
    float* ob = out + (size_t)b * 2 * TOPK * 5;
    for (int i = t; i < TOPK * 5; i += NTHR) ob[i] = 0.0f;
    if (t < TOPK) {
        float f = skeep[t] ? 1.0f : 0.0f;
        float* r = ob + TOPK * 5 + t * 5;
        r[0] = sscore[t] * f;
        r[1] = sbox[t * 4 + 0] * f;
        r[2] = sbox[t * 4 + 1] * f;
        r[3] = sbox[t * 4 + 2] * f;
        r[4] = sbox[t * 4 + 3] * f;
    }
}

extern "C" void kernel_launch(void* const* d_in, const int* in_sizes, int n_in,
                              void* d_out, int out_size) {
    const float* loc    = (const float*)d_in[0];
    const float* conf   = (const float*)d_in[1];
    const float* priors = (const float*)d_in[2];
    float* out = (float*)d_out;

    k_all<<<BATCH, NTHR>>>(loc, priors, conf, out);
}